// round 2
// baseline (speedup 1.0000x reference)
#include <cuda_runtime.h>
#include <math.h>

#define B_DIM 4096
#define M_DIM 512
#define P_DIM 2048
#define N_LAYERS 30
#define STEP_C 0.1f
#define THR_C 0.01f   // LAM * STEP

// Scratch state (allocation-free rule: __device__ globals)
__device__ float g_Z[(size_t)B_DIM * P_DIM];   // 32 MB: z codes [B, P]
__device__ float g_R[(size_t)B_DIM * M_DIM];   // 8 MB: residual Wz - x [B, M]

#define TBM 128
#define TBN 128
#define TBK 16
#define TPAD 132   // padded smem row stride (floats); keeps 16B alignment, kills bank conflicts

__device__ __forceinline__ float softthr(float v) {
    return copysignf(fmaxf(fabsf(v) - THR_C, 0.0f), v);
}

// ---------------------------------------------------------------------------
// NT GEMM: C[r, c] = sum_k g_Z[r*P + k] * W[c*P + k]   (both operands K-contig)
//   SUB = true : C := g_R = Z*W^T - X   (residual)
//   SUB = false: C := Cout = Z*W^T      (decode xhat)
// Output ld = M_DIM. Grid: (M/128, B/128). 256 threads, 8x8 microtile.
// Double-buffered smem: one __syncthreads per K-chunk.
// ---------------------------------------------------------------------------
template <bool SUB>
__global__ __launch_bounds__(256, 2) void gemm_nt_kernel(
    const float* __restrict__ W, const float* __restrict__ X,
    float* __restrict__ Cout)
{
    __shared__ float As[2][TBK][TPAD];
    __shared__ float Bs[2][TBK][TPAD];

    const int tid = threadIdx.x;
    const int tx = tid & 15;
    const int ty = tid >> 4;
    const int rowBase = blockIdx.y * TBM;
    const int colBase = blockIdx.x * TBN;

    // loader mapping: 256 threads cover 128 rows x 16 k as 2 x float4 each
    const int ar0 = tid >> 2;          // 0..63
    const int ak0 = (tid & 3) << 2;    // 0,4,8,12
    const int ar1 = ar0 + 64;          // 64..127

    const float* Ag = g_Z + (size_t)rowBase * P_DIM;
    const float* Bg = W + (size_t)colBase * P_DIM;

    float acc[8][8];
#pragma unroll
    for (int i = 0; i < 8; i++)
#pragma unroll
        for (int j = 0; j < 8; j++) acc[i][j] = 0.0f;

    const int nk = P_DIM / TBK;

    // prologue: load chunk 0 into buffer 0
    {
        float4 va0 = *(const float4*)(Ag + (size_t)ar0 * P_DIM + ak0);
        float4 va1 = *(const float4*)(Ag + (size_t)ar1 * P_DIM + ak0);
        float4 vb0 = *(const float4*)(Bg + (size_t)ar0 * P_DIM + ak0);
        float4 vb1 = *(const float4*)(Bg + (size_t)ar1 * P_DIM + ak0);
        As[0][ak0 + 0][ar0] = va0.x; As[0][ak0 + 1][ar0] = va0.y;
        As[0][ak0 + 2][ar0] = va0.z; As[0][ak0 + 3][ar0] = va0.w;
        As[0][ak0 + 0][ar1] = va1.x; As[0][ak0 + 1][ar1] = va1.y;
        As[0][ak0 + 2][ar1] = va1.z; As[0][ak0 + 3][ar1] = va1.w;
        Bs[0][ak0 + 0][ar0] = vb0.x; Bs[0][ak0 + 1][ar0] = vb0.y;
        Bs[0][ak0 + 2][ar0] = vb0.z; Bs[0][ak0 + 3][ar0] = vb0.w;
        Bs[0][ak0 + 0][ar1] = vb1.x; Bs[0][ak0 + 1][ar1] = vb1.y;
        Bs[0][ak0 + 2][ar1] = vb1.z; Bs[0][ak0 + 3][ar1] = vb1.w;
    }
    __syncthreads();

    for (int kk = 0; kk < nk; kk++) {
        const int cur = kk & 1;
        const int nxt = cur ^ 1;

        // prefetch next chunk into the other buffer (no barrier needed before
        // stores: that buffer was last READ in iteration kk-1, and the
        // __syncthreads at the end of kk-1 ordered those reads).
        if (kk + 1 < nk) {
            const int ko = (kk + 1) * TBK + ak0;
            float4 va0 = *(const float4*)(Ag + (size_t)ar0 * P_DIM + ko);
            float4 va1 = *(const float4*)(Ag + (size_t)ar1 * P_DIM + ko);
            float4 vb0 = *(const float4*)(Bg + (size_t)ar0 * P_DIM + ko);
            float4 vb1 = *(const float4*)(Bg + (size_t)ar1 * P_DIM + ko);
            As[nxt][ak0 + 0][ar0] = va0.x; As[nxt][ak0 + 1][ar0] = va0.y;
            As[nxt][ak0 + 2][ar0] = va0.z; As[nxt][ak0 + 3][ar0] = va0.w;
            As[nxt][ak0 + 0][ar1] = va1.x; As[nxt][ak0 + 1][ar1] = va1.y;
            As[nxt][ak0 + 2][ar1] = va1.z; As[nxt][ak0 + 3][ar1] = va1.w;
            Bs[nxt][ak0 + 0][ar0] = vb0.x; Bs[nxt][ak0 + 1][ar0] = vb0.y;
            Bs[nxt][ak0 + 2][ar0] = vb0.z; Bs[nxt][ak0 + 3][ar0] = vb0.w;
            Bs[nxt][ak0 + 0][ar1] = vb1.x; Bs[nxt][ak0 + 1][ar1] = vb1.y;
            Bs[nxt][ak0 + 2][ar1] = vb1.z; Bs[nxt][ak0 + 3][ar1] = vb1.w;
        }

#pragma unroll
        for (int k = 0; k < TBK; k++) {
            float4 a0 = *(const float4*)&As[cur][k][ty * 4];
            float4 a1 = *(const float4*)&As[cur][k][ty * 4 + 64];
            float4 b0 = *(const float4*)&Bs[cur][k][tx * 4];
            float4 b1 = *(const float4*)&Bs[cur][k][tx * 4 + 64];
            float av[8] = {a0.x, a0.y, a0.z, a0.w, a1.x, a1.y, a1.z, a1.w};
            float bv[8] = {b0.x, b0.y, b0.z, b0.w, b1.x, b1.y, b1.z, b1.w};
#pragma unroll
            for (int i = 0; i < 8; i++)
#pragma unroll
                for (int j = 0; j < 8; j++)
                    acc[i][j] = fmaf(av[i], bv[j], acc[i][j]);
        }
        __syncthreads();   // reads of 'cur' done; writes of 'nxt' visible
    }

    float* C = SUB ? g_R : Cout;
#pragma unroll
    for (int ii = 0; ii < 2; ii++)
#pragma unroll
        for (int i = 0; i < 4; i++) {
            const int r = rowBase + ii * 64 + ty * 4 + i;
            float* crow = C + (size_t)r * M_DIM;
            const float* xrow = X + (size_t)r * M_DIM;
#pragma unroll
            for (int jj = 0; jj < 2; jj++) {
                const int c = colBase + jj * 64 + tx * 4;
                float4 v;
                v.x = acc[ii * 4 + i][jj * 4 + 0];
                v.y = acc[ii * 4 + i][jj * 4 + 1];
                v.z = acc[ii * 4 + i][jj * 4 + 2];
                v.w = acc[ii * 4 + i][jj * 4 + 3];
                if (SUB) {
                    float4 xv = *(const float4*)&xrow[c];
                    v.x -= xv.x; v.y -= xv.y; v.z -= xv.z; v.w -= xv.w;
                }
                *(float4*)&crow[c] = v;
            }
        }
}

// ---------------------------------------------------------------------------
// NN GEMM + fused ISTA update:
//   U[b, p] = sum_m g_R[b*M + m] * W[m*P + p]
//   g_Z[b, p] = softthr(g_Z[b, p] - 0.1 * U[b, p])
// Grid: (P/128, B/128). Double-buffered smem.
// ---------------------------------------------------------------------------
__global__ __launch_bounds__(256, 2) void gemm_nn_update_kernel(
    const float* __restrict__ W)
{
    __shared__ float As[2][TBK][TPAD];
    __shared__ float Bs[2][TBK][TPAD];

    const int tid = threadIdx.x;
    const int tx = tid & 15;
    const int ty = tid >> 4;
    const int rowBase = blockIdx.y * TBM;
    const int colBase = blockIdx.x * TBN;

    // A loader (g_R, K-contig): 128 rows x 16 k
    const int ar0 = tid >> 2;
    const int ak0 = (tid & 3) << 2;
    const int ar1 = ar0 + 64;
    // B loader (W, N-contig rows of k): 16 k-rows x 128 n
    const int kr0 = tid >> 5;          // 0..7
    const int n40 = (tid & 31) << 2;   // 0..124
    const int kr1 = kr0 + 8;           // 8..15

    const float* Ag = g_R + (size_t)rowBase * M_DIM;
    const float* Bg = W + colBase;

    float acc[8][8];
#pragma unroll
    for (int i = 0; i < 8; i++)
#pragma unroll
        for (int j = 0; j < 8; j++) acc[i][j] = 0.0f;

    const int nk = M_DIM / TBK;

    {
        float4 va0 = *(const float4*)(Ag + (size_t)ar0 * M_DIM + ak0);
        float4 va1 = *(const float4*)(Ag + (size_t)ar1 * M_DIM + ak0);
        float4 vb0 = *(const float4*)(Bg + (size_t)kr0 * P_DIM + n40);
        float4 vb1 = *(const float4*)(Bg + (size_t)kr1 * P_DIM + n40);
        As[0][ak0 + 0][ar0] = va0.x; As[0][ak0 + 1][ar0] = va0.y;
        As[0][ak0 + 2][ar0] = va0.z; As[0][ak0 + 3][ar0] = va0.w;
        As[0][ak0 + 0][ar1] = va1.x; As[0][ak0 + 1][ar1] = va1.y;
        As[0][ak0 + 2][ar1] = va1.z; As[0][ak0 + 3][ar1] = va1.w;
        *(float4*)&Bs[0][kr0][n40] = vb0;
        *(float4*)&Bs[0][kr1][n40] = vb1;
    }
    __syncthreads();

    for (int kk = 0; kk < nk; kk++) {
        const int cur = kk & 1;
        const int nxt = cur ^ 1;

        if (kk + 1 < nk) {
            const int ko = (kk + 1) * TBK;
            float4 va0 = *(const float4*)(Ag + (size_t)ar0 * M_DIM + ko + ak0);
            float4 va1 = *(const float4*)(Ag + (size_t)ar1 * M_DIM + ko + ak0);
            float4 vb0 = *(const float4*)(Bg + (size_t)(ko + kr0) * P_DIM + n40);
            float4 vb1 = *(const float4*)(Bg + (size_t)(ko + kr1) * P_DIM + n40);
            As[nxt][ak0 + 0][ar0] = va0.x; As[nxt][ak0 + 1][ar0] = va0.y;
            As[nxt][ak0 + 2][ar0] = va0.z; As[nxt][ak0 + 3][ar0] = va0.w;
            As[nxt][ak0 + 0][ar1] = va1.x; As[nxt][ak0 + 1][ar1] = va1.y;
            As[nxt][ak0 + 2][ar1] = va1.z; As[nxt][ak0 + 3][ar1] = va1.w;
            *(float4*)&Bs[nxt][kr0][n40] = vb0;
            *(float4*)&Bs[nxt][kr1][n40] = vb1;
        }

#pragma unroll
        for (int k = 0; k < TBK; k++) {
            float4 a0 = *(const float4*)&As[cur][k][ty * 4];
            float4 a1 = *(const float4*)&As[cur][k][ty * 4 + 64];
            float4 b0 = *(const float4*)&Bs[cur][k][tx * 4];
            float4 b1 = *(const float4*)&Bs[cur][k][tx * 4 + 64];
            float av[8] = {a0.x, a0.y, a0.z, a0.w, a1.x, a1.y, a1.z, a1.w};
            float bv[8] = {b0.x, b0.y, b0.z, b0.w, b1.x, b1.y, b1.z, b1.w};
#pragma unroll
            for (int i = 0; i < 8; i++)
#pragma unroll
                for (int j = 0; j < 8; j++)
                    acc[i][j] = fmaf(av[i], bv[j], acc[i][j]);
        }
        __syncthreads();
    }

#pragma unroll
    for (int ii = 0; ii < 2; ii++)
#pragma unroll
        for (int i = 0; i < 4; i++) {
            const int r = rowBase + ii * 64 + ty * 4 + i;
            float* zrow = g_Z + (size_t)r * P_DIM;
#pragma unroll
            for (int jj = 0; jj < 2; jj++) {
                const int c = colBase + jj * 64 + tx * 4;
                float4 z = *(float4*)&zrow[c];
                z.x = softthr(fmaf(-STEP_C, acc[ii * 4 + i][jj * 4 + 0], z.x));
                z.y = softthr(fmaf(-STEP_C, acc[ii * 4 + i][jj * 4 + 1], z.y));
                z.z = softthr(fmaf(-STEP_C, acc[ii * 4 + i][jj * 4 + 2], z.z));
                z.w = softthr(fmaf(-STEP_C, acc[ii * 4 + i][jj * 4 + 3], z.w));
                *(float4*)&zrow[c] = z;
            }
        }
}

__global__ void zero_z_kernel() {
    const size_t n = (size_t)B_DIM * P_DIM / 4;
    float4 zero4 = make_float4(0.f, 0.f, 0.f, 0.f);
    for (size_t i = (size_t)blockIdx.x * blockDim.x + threadIdx.x; i < n;
         i += (size_t)gridDim.x * blockDim.x)
        ((float4*)g_Z)[i] = zero4;
}

__global__ void copy_z_kernel(float* __restrict__ out) {
    const size_t n = (size_t)B_DIM * P_DIM / 4;
    for (size_t i = (size_t)blockIdx.x * blockDim.x + threadIdx.x; i < n;
         i += (size_t)gridDim.x * blockDim.x)
        ((float4*)out)[i] = ((const float4*)g_Z)[i];
}

extern "C" void kernel_launch(void* const* d_in, const int* in_sizes, int n_in,
                              void* d_out, int out_size)
{
    const float* x = (const float*)d_in[0];   // [B, M, 1] = 2097152 f32
    const float* W = (const float*)d_in[1];   // [M, P]    = 1048576 f32
    float* out = (float*)d_out;               // xhat (B*M) then z (B*P)

    (void)in_sizes; (void)n_in; (void)out_size;

    zero_z_kernel<<<1024, 256>>>();

    dim3 gA(M_DIM / TBN, B_DIM / TBM);   // (4, 32)  -> 128 CTAs
    dim3 gB(P_DIM / TBN, B_DIM / TBM);   // (16, 32) -> 512 CTAs

    for (int l = 0; l < N_LAYERS; l++) {
        gemm_nt_kernel<true><<<gA, 256>>>(W, x, nullptr);   // R = Z*W^T - X
        gemm_nn_update_kernel<<<gB, 256>>>(W);              // Z = soft(Z - 0.1*R*W)
    }

    gemm_nt_kernel<false><<<gA, 256>>>(W, x, out);          // xhat = Z*W^T
    copy_z_kernel<<<2048, 256>>>(out + (size_t)B_DIM * M_DIM);
}

// round 15
// speedup vs baseline: 1.1289x; 1.1289x over previous
#include <cuda_runtime.h>
#include <math.h>

#define B_DIM 4096
#define M_DIM 512
#define P_DIM 2048
#define N_LAYERS 30
#define STEP_C 0.1f
#define THR_C 0.01f

// Scratch state (allocation-free rule: __device__ globals) — 40 MB, proven good
__device__ float g_Z[(size_t)B_DIM * P_DIM];   // 32 MB: z codes [B, P]
__device__ float g_R[(size_t)B_DIM * M_DIM];   // 8 MB: residual Wz - x [B, M]

#define TBK 16
#define TPAD 132   // padded smem row stride (floats)

__device__ __forceinline__ float softthr(float v) {
    return copysignf(fmaxf(fabsf(v) - THR_C, 0.0f), v);
}

// ---------------------------------------------------------------------------
// NT64 GEMM: C[r, c] = sum_k g_Z[r*P + k] * W[c*P + k]  (both K-contig)
//   SUB = true : g_R = Z*W^T - X   (residual)
//   SUB = false: Cout = Z*W^T      (decode xhat)
// Tile 128m x 64n, 256 threads, 8x4 microtile -> acc 32 regs (low pressure).
// Grid: (M/64, B/128) = (8, 32) = 256 CTAs.
// ---------------------------------------------------------------------------
template <bool SUB>
__global__ __launch_bounds__(256, 2) void gemm_nt64_kernel(
    const float* __restrict__ W, const float* __restrict__ X,
    float* __restrict__ Cout)
{
    __shared__ float As[TBK][TPAD];
    __shared__ float Bs[TBK][68];

    const int tid = threadIdx.x;
    const int tx = tid & 15;            // 16 n-groups of 4
    const int ty = tid >> 4;            // 16 m-groups of 4 (x2 blocks)
    const int rowBase = blockIdx.y * 128;
    const int colBase = blockIdx.x * 64;

    // A loader: 256 threads cover 128 rows x 16 k as 2 x float4 each
    const int ar0 = tid >> 2;           // 0..63
    const int ak0 = (tid & 3) << 2;     // 0,4,8,12
    const int ar1 = ar0 + 64;           // 64..127
    // B loader: 64 rows x 16 k as 1 x float4 each
    const int br = tid >> 2;            // 0..63
    const int bk = (tid & 3) << 2;      // 0,4,8,12

    const float* Ag = g_Z + (size_t)rowBase * P_DIM;
    const float* Bg = W + (size_t)colBase * P_DIM;

    float acc[8][4];
#pragma unroll
    for (int i = 0; i < 8; i++)
#pragma unroll
        for (int j = 0; j < 4; j++) acc[i][j] = 0.0f;

    const int nk = P_DIM / TBK;

    // prologue stage (chunk 0)
    float4 va0 = *(const float4*)(Ag + (size_t)ar0 * P_DIM + ak0);
    float4 va1 = *(const float4*)(Ag + (size_t)ar1 * P_DIM + ak0);
    float4 vb0 = *(const float4*)(Bg + (size_t)br * P_DIM + bk);

    for (int kk = 0; kk < nk; kk++) {
        // store staged tile (transposed: smem is [k][row])
        As[ak0 + 0][ar0] = va0.x; As[ak0 + 1][ar0] = va0.y;
        As[ak0 + 2][ar0] = va0.z; As[ak0 + 3][ar0] = va0.w;
        As[ak0 + 0][ar1] = va1.x; As[ak0 + 1][ar1] = va1.y;
        As[ak0 + 2][ar1] = va1.z; As[ak0 + 3][ar1] = va1.w;
        Bs[bk + 0][br] = vb0.x; Bs[bk + 1][br] = vb0.y;
        Bs[bk + 2][br] = vb0.z; Bs[bk + 3][br] = vb0.w;
        __syncthreads();

        if (kk + 1 < nk) {  // prefetch next chunk into regs, overlaps compute
            const int ko = (kk + 1) * TBK;
            va0 = *(const float4*)(Ag + (size_t)ar0 * P_DIM + ko + ak0);
            va1 = *(const float4*)(Ag + (size_t)ar1 * P_DIM + ko + ak0);
            vb0 = *(const float4*)(Bg + (size_t)br * P_DIM + ko + bk);
        }

#pragma unroll
        for (int k = 0; k < TBK; k++) {
            float4 a0 = *(const float4*)&As[k][ty * 4];
            float4 a1 = *(const float4*)&As[k][ty * 4 + 64];
            float4 b0 = *(const float4*)&Bs[k][tx * 4];
            float av[8] = {a0.x, a0.y, a0.z, a0.w, a1.x, a1.y, a1.z, a1.w};
            float bv[4] = {b0.x, b0.y, b0.z, b0.w};
#pragma unroll
            for (int i = 0; i < 8; i++)
#pragma unroll
                for (int j = 0; j < 4; j++)
                    acc[i][j] = fmaf(av[i], bv[j], acc[i][j]);
        }
        __syncthreads();
    }

    float* C = SUB ? g_R : Cout;
#pragma unroll
    for (int ii = 0; ii < 2; ii++)
#pragma unroll
        for (int i = 0; i < 4; i++) {
            const int r = rowBase + ii * 64 + ty * 4 + i;
            float* crow = C + (size_t)r * M_DIM;
            const float* xrow = X + (size_t)r * M_DIM;
            const int c = colBase + tx * 4;
            float4 v;
            v.x = acc[ii * 4 + i][0];
            v.y = acc[ii * 4 + i][1];
            v.z = acc[ii * 4 + i][2];
            v.w = acc[ii * 4 + i][3];
            if (SUB) {
                float4 xv = *(const float4*)&xrow[c];
                v.x -= xv.x; v.y -= xv.y; v.z -= xv.z; v.w -= xv.w;
            }
            *(float4*)&crow[c] = v;
        }
}

// ---------------------------------------------------------------------------
// NN GEMM + fused ISTA update (BYTE-IDENTICAL to the R2-passing kernel):
//   U[b, p] = sum_m g_R[b*M + m] * W[m*P + p]
//   g_Z[b, p] = softthr(g_Z[b, p] - 0.1 * U[b, p])
// Grid: (P/128, B/128).
// ---------------------------------------------------------------------------
__global__ __launch_bounds__(256, 2) void gemm_nn_update_kernel(
    const float* __restrict__ W)
{
    __shared__ float As[TBK][TPAD];
    __shared__ float Bs[TBK][TPAD];

    const int tid = threadIdx.x;
    const int tx = tid & 15;
    const int ty = tid >> 4;
    const int rowBase = blockIdx.y * 128;
    const int colBase = blockIdx.x * 128;

    // A loader (g_R, K-contig): 128 rows x 16 k
    const int ar0 = tid >> 2;
    const int ak0 = (tid & 3) << 2;
    const int ar1 = ar0 + 64;
    // B loader (W, N-contig rows of k): 16 k-rows x 128 n
    const int kr0 = tid >> 5;          // 0..7
    const int n40 = (tid & 31) << 2;   // 0..124
    const int kr1 = kr0 + 8;           // 8..15

    const float* Ag = g_R + (size_t)rowBase * M_DIM;
    const float* Bg = W + colBase;

    float acc[8][8];
#pragma unroll
    for (int i = 0; i < 8; i++)
#pragma unroll
        for (int j = 0; j < 8; j++) acc[i][j] = 0.0f;

    const int nk = M_DIM / TBK;

    float4 va0 = *(const float4*)(Ag + (size_t)ar0 * M_DIM + ak0);
    float4 va1 = *(const float4*)(Ag + (size_t)ar1 * M_DIM + ak0);
    float4 vb0 = *(const float4*)(Bg + (size_t)kr0 * P_DIM + n40);
    float4 vb1 = *(const float4*)(Bg + (size_t)kr1 * P_DIM + n40);

    for (int kk = 0; kk < nk; kk++) {
        As[ak0 + 0][ar0] = va0.x; As[ak0 + 1][ar0] = va0.y;
        As[ak0 + 2][ar0] = va0.z; As[ak0 + 3][ar0] = va0.w;
        As[ak0 + 0][ar1] = va1.x; As[ak0 + 1][ar1] = va1.y;
        As[ak0 + 2][ar1] = va1.z; As[ak0 + 3][ar1] = va1.w;
        *(float4*)&Bs[kr0][n40] = vb0;
        *(float4*)&Bs[kr1][n40] = vb1;
        __syncthreads();

        if (kk + 1 < nk) {
            const int ko = (kk + 1) * TBK;
            va0 = *(const float4*)(Ag + (size_t)ar0 * M_DIM + ko + ak0);
            va1 = *(const float4*)(Ag + (size_t)ar1 * M_DIM + ko + ak0);
            vb0 = *(const float4*)(Bg + (size_t)(ko + kr0) * P_DIM + n40);
            vb1 = *(const float4*)(Bg + (size_t)(ko + kr1) * P_DIM + n40);
        }

#pragma unroll
        for (int k = 0; k < TBK; k++) {
            float4 a0 = *(const float4*)&As[k][ty * 4];
            float4 a1 = *(const float4*)&As[k][ty * 4 + 64];
            float4 b0 = *(const float4*)&Bs[k][tx * 4];
            float4 b1 = *(const float4*)&Bs[k][tx * 4 + 64];
            float av[8] = {a0.x, a0.y, a0.z, a0.w, a1.x, a1.y, a1.z, a1.w};
            float bv[8] = {b0.x, b0.y, b0.z, b0.w, b1.x, b1.y, b1.z, b1.w};
#pragma unroll
            for (int i = 0; i < 8; i++)
#pragma unroll
                for (int j = 0; j < 8; j++)
                    acc[i][j] = fmaf(av[i], bv[j], acc[i][j]);
        }
        __syncthreads();
    }

#pragma unroll
    for (int ii = 0; ii < 2; ii++)
#pragma unroll
        for (int i = 0; i < 4; i++) {
            const int r = rowBase + ii * 64 + ty * 4 + i;
            float* zrow = g_Z + (size_t)r * P_DIM;
#pragma unroll
            for (int jj = 0; jj < 2; jj++) {
                const int c = colBase + jj * 64 + tx * 4;
                float4 z = *(float4*)&zrow[c];
                z.x = softthr(fmaf(-STEP_C, acc[ii * 4 + i][jj * 4 + 0], z.x));
                z.y = softthr(fmaf(-STEP_C, acc[ii * 4 + i][jj * 4 + 1], z.y));
                z.z = softthr(fmaf(-STEP_C, acc[ii * 4 + i][jj * 4 + 2], z.z));
                z.w = softthr(fmaf(-STEP_C, acc[ii * 4 + i][jj * 4 + 3], z.w));
                *(float4*)&zrow[c] = z;
            }
        }
}

__global__ void zero_z_kernel() {
    const size_t n = (size_t)B_DIM * P_DIM / 4;
    float4 zero4 = make_float4(0.f, 0.f, 0.f, 0.f);
    for (size_t i = (size_t)blockIdx.x * blockDim.x + threadIdx.x; i < n;
         i += (size_t)gridDim.x * blockDim.x)
        ((float4*)g_Z)[i] = zero4;
}

__global__ void copy_z_kernel(float* __restrict__ out) {
    const size_t n = (size_t)B_DIM * P_DIM / 4;
    for (size_t i = (size_t)blockIdx.x * blockDim.x + threadIdx.x; i < n;
         i += (size_t)gridDim.x * blockDim.x)
        ((float4*)out)[i] = ((const float4*)g_Z)[i];
}

extern "C" void kernel_launch(void* const* d_in, const int* in_sizes, int n_in,
                              void* d_out, int out_size)
{
    const float* x = (const float*)d_in[0];   // [B, M, 1] = 2097152 f32
    const float* W = (const float*)d_in[1];   // [M, P]    = 1048576 f32
    float* out = (float*)d_out;               // xhat (B*M) then z (B*P)

    (void)in_sizes; (void)n_in; (void)out_size;

    zero_z_kernel<<<1024, 256>>>();

    dim3 gA(M_DIM / 64, B_DIM / 128);    // (8, 32)  -> 256 CTAs
    dim3 gB(P_DIM / 128, B_DIM / 128);   // (16, 32) -> 512 CTAs

    for (int l = 0; l < N_LAYERS; l++) {
        gemm_nt64_kernel<true><<<gA, 256>>>(W, x, nullptr);  // R = Z*W^T - X
        gemm_nn_update_kernel<<<gB, 256>>>(W);               // Z = soft(Z - 0.1*R*W)
    }

    gemm_nt64_kernel<false><<<gA, 256>>>(W, x, out);         // xhat = Z*W^T
    copy_z_kernel<<<2048, 256>>>(out + (size_t)B_DIM * M_DIM);
}